// round 14
// baseline (speedup 1.0000x reference)
#include <cuda_runtime.h>
#include <cuda_fp16.h>
#include <math.h>

#define NN 100000
#define EE 1600000
#define NSB ((NN + 511) / 512)   // 196 scan blocks
#define NZB ((NN + 255) / 256)   // 391 zero blocks

// ---------------- scratch (device globals; no allocation allowed) ------------
__device__ __half g_hh [(size_t)NN * 64];    // GAT h (fp16, for agg gather)
__device__ __half g_x3h[(size_t)NN * 64];    // aggregated GAT output (fp16)
__device__ float  g_as [NN];
__device__ float  g_ad [NN];
__device__ float  g_dsum[NN];                // softmax denominator (edge part)
__device__ int    g_cnt[NN];                 // in-degree
__device__ int    g_off[NN];                 // CSR row offsets
__device__ int    g_pos[NN];                 // scatter cursors
__device__ float2 g_edge[EE];                // CSR (src bit-cast, exp) pairs
__device__ int    g_bsum[NSB], g_boff[NSB];
__device__ float  g_u1[384], g_u2[384], g_cc[384];
__device__ __half g_w1t[384 * 64];           // fc1_w[128:192,:]^T fp16 [n][k]
__device__ __half g_w2t[128 * 384];          // fc2_w^T fp16            [n][k]
__device__ __half g_w3t[64 * 128];           // fc3_w^T fp16            [n][k]
__device__ int    g_is64;

// ---------------- fused setup: zero / detect / prep / transpose --------------
__global__ void setup_kernel(const unsigned* __restrict__ p,
                             const float* __restrict__ w1, const float* __restrict__ b1,
                             const float* __restrict__ w2, const float* __restrict__ b2,
                             const float* __restrict__ gatb,
                             const float* __restrict__ fc1w, const float* __restrict__ fc1b,
                             const float* __restrict__ fc2w, const float* __restrict__ fc3w) {
    __shared__ unsigned sh[256];
    int b = blockIdx.x, t = threadIdx.x;
    if (b < NZB) {
        int i = b * 256 + t;
        if (i < NN) { g_cnt[i] = 0; g_as[i] = 0.f; g_ad[i] = 0.f; g_dsum[i] = 0.f; }
        return;
    }
    if (b == NZB) {   // int64 detection: high words all zero => int64
        sh[t] = p[2 * t + 1];
        __syncthreads();
        if (t == 0) {
            unsigned o = 0;
            for (int i = 0; i < 256; i++) o |= sh[i];
            g_is64 = (o == 0) ? 1 : 0;
        }
        return;
    }
    if (b <= NZB + 2) {  // prep: rank-2 epilogue vectors (192 cols per block)
        if (t < 192) {
            int k = (b - (NZB + 1)) * 192 + t;
            float s1 = 0.f, s2 = 0.f, c = fc1b[k];
            for (int j = 0; j < 64; j++) {
                float wa = fc1w[(size_t)j * 384 + k];
                float wb = fc1w[(size_t)(64 + j) * 384 + k];
                float wc = fc1w[(size_t)(128 + j) * 384 + k];
                s1 += w1[j] * wa;
                s2 += w2[j] * wb;
                c  += b1[j] * wa + b2[j] * wb + gatb[j] * wc;
            }
            g_u1[k] = s1; g_u2[k] = s2; g_cc[k] = c;
        }
        return;
    }
    // weight transpose + fp16 cast
    int i = (b - (NZB + 3)) * 256 + t;
    if (i < 384 * 64) {                       // g_w1t[c][k] = fc1w[128+k][c]
        int c = i >> 6, k = i & 63;
        g_w1t[i] = __float2half_rn(fc1w[(size_t)(128 + k) * 384 + c]);
    }
    if (i < 128 * 384) {                      // g_w2t[c][k] = fc2w[k][c]
        int c = i / 384, k = i % 384;
        g_w2t[i] = __float2half_rn(fc2w[(size_t)k * 128 + c]);
    }
    if (i < 64 * 128) {                       // g_w3t[c][k] = fc3w[k][c]
        int c = i >> 7, k = i & 127;
        g_w3t[i] = __float2half_rn(fc3w[(size_t)k * 64 + c]);
    }
}

// ---------------- degree histogram -------------------------------------------
__global__ void hist_kernel(const void* __restrict__ idx) {
    int e = blockIdx.x * blockDim.x + threadIdx.x;
    if (e >= EE) return;
    int d = g_is64 ? (int)((const long long*)idx)[EE + e]
                   : ((const int*)idx)[EE + e];
    atomicAdd(&g_cnt[d], 1);
}

// ---------------- 3-kernel exclusive scan over g_cnt -------------------------
__global__ void scan1_kernel() {
    __shared__ int sh[256];
    int b = blockIdx.x, t = threadIdx.x;
    int i0 = b * 512 + t;
    int v = 0;
    if (i0 < NN) v += g_cnt[i0];
    if (i0 + 256 < NN) v += g_cnt[i0 + 256];
    sh[t] = v; __syncthreads();
    for (int o = 128; o; o >>= 1) { if (t < o) sh[t] += sh[t + o]; __syncthreads(); }
    if (t == 0) g_bsum[b] = sh[0];
}

__global__ void scan2_kernel() {
    __shared__ int sh[256];
    int t = threadIdx.x;
    int v = (t < NSB) ? g_bsum[t] : 0;
    sh[t] = v;
    for (int o = 1; o < 256; o <<= 1) {
        __syncthreads();
        int u = (t >= o) ? sh[t - o] : 0;
        __syncthreads();
        sh[t] += u;
    }
    __syncthreads();
    if (t < NSB) g_boff[t] = sh[t] - v;
}

__global__ void scan3_kernel() {
    __shared__ int sh[512];
    int b = blockIdx.x, t = threadIdx.x;
    int i = b * 512 + t;
    int c = (i < NN) ? g_cnt[i] : 0;
    sh[t] = c;
    for (int o = 1; o < 512; o <<= 1) {
        __syncthreads();
        int u = (t >= o) ? sh[t - o] : 0;
        __syncthreads();
        sh[t] += u;
    }
    __syncthreads();
    if (i < NN) {
        int excl = sh[t] - c + g_boff[b];
        g_off[i] = excl;
        g_pos[i] = excl;
    }
}

// ---------------- scatter: packed (src, exp) + denominator atomics -----------
__global__ void scatter_kernel(const void* __restrict__ idx) {
    int e = blockIdx.x * blockDim.x + threadIdx.x;
    if (e >= EE) return;
    int s, d;
    if (g_is64) {
        const long long* q = (const long long*)idx;
        s = (int)q[e]; d = (int)q[EE + e];
    } else {
        const int* q = (const int*)idx;
        s = q[e]; d = q[EE + e];
    }
    float v = g_as[s] + g_ad[d];
    v = (v > 0.f) ? v : 0.2f * v;
    float ex = expf(v);
    int p = atomicAdd(&g_pos[d], 1);
    atomicAdd(&g_dsum[d], ex);
    g_edge[p] = make_float2(__int_as_float(s), ex);
}

// ---------------- CSR aggregation: warp per node, single pass ----------------
__global__ void agg_kernel() {
    int node = (int)((blockIdx.x * (size_t)blockDim.x + threadIdx.x) >> 5);
    int lane = threadIdx.x & 31;
    if (node >= NN) return;
    int beg = g_off[node];
    int cnt = g_cnt[node];
    float v = g_as[node] + g_ad[node];
    v = (v > 0.f) ? v : 0.2f * v;
    float ex_self = expf(v);
    float invd = 1.f / (g_dsum[node] + ex_self + 1e-16f);
    float2 acc;
    {
        half2 hv = *(const half2*)(g_hh + (size_t)node * 64 + lane * 2);
        float2 f = __half22float2(hv);
        float c = ex_self * invd;
        acc.x = c * f.x; acc.y = c * f.y;
    }
#pragma unroll 4
    for (int e = 0; e < cnt; e++) {
        float2 ev = g_edge[beg + e];
        int s = __float_as_int(ev.x);
        float c = ev.y * invd;
        half2 hv = *(const half2*)(g_hh + (size_t)s * 64 + lane * 2);
        float2 f = __half22float2(hv);
        acc.x += c * f.x; acc.y += c * f.y;
    }
    *(half2*)(g_x3h + (size_t)node * 64 + lane * 2) = __floats2half2_rn(acc.x, acc.y);
}

// ---------------- TF32 / fp16 / cp.async helpers -------------------------------
__device__ __forceinline__ unsigned f2tf(float x) {
    unsigned r; asm("cvt.rna.tf32.f32 %0, %1;" : "=r"(r) : "f"(x)); return r;
}
__device__ __forceinline__ void mma_tf32(float* d, const unsigned* a, const unsigned* b) {
    asm volatile(
        "mma.sync.aligned.m16n8k8.row.col.f32.tf32.tf32.f32 "
        "{%0,%1,%2,%3}, {%4,%5,%6,%7}, {%8,%9}, {%0,%1,%2,%3};\n"
        : "+f"(d[0]), "+f"(d[1]), "+f"(d[2]), "+f"(d[3])
        : "r"(a[0]), "r"(a[1]), "r"(a[2]), "r"(a[3]), "r"(b[0]), "r"(b[1]));
}
__device__ __forceinline__ void mma_f16(float* d, const unsigned* a, const unsigned* b) {
    asm volatile(
        "mma.sync.aligned.m16n8k16.row.col.f32.f16.f16.f32 "
        "{%0,%1,%2,%3}, {%4,%5,%6,%7}, {%8,%9}, {%0,%1,%2,%3};\n"
        : "+f"(d[0]), "+f"(d[1]), "+f"(d[2]), "+f"(d[3])
        : "r"(a[0]), "r"(a[1]), "r"(a[2]), "r"(a[3]), "r"(b[0]), "r"(b[1]));
}
__device__ __forceinline__ void cp16(void* smem, const void* g, bool valid) {
    unsigned sa = (unsigned)__cvta_generic_to_shared(smem);
    int sz = valid ? 16 : 0;
    asm volatile("cp.async.cg.shared.global [%0], [%1], 16, %2;" :: "r"(sa), "l"(g), "r"(sz));
}
__device__ __forceinline__ void cp8(void* smem, const void* g, bool valid) {
    unsigned sa = (unsigned)__cvta_generic_to_shared(smem);
    int sz = valid ? 8 : 0;
    asm volatile("cp.async.ca.shared.global [%0], [%1], 8, %2;" :: "r"(sa), "l"(g), "r"(sz));
}
#define CP_COMMIT() asm volatile("cp.async.commit_group;")
#define CP_WAIT1()  asm volatile("cp.async.wait_group 1;")
#define CP_WAIT0()  asm volatile("cp.async.wait_group 0;")

// ---------------- fused MLP: fc1 -> fc2 -> fc3, 512 threads -------------------
// Block owns 128 rows; 16 warps in 4m x 4n grid, warp tile 32x32 (m16n8k16).
#define FM_WSZ   (128 * 72)
#define FM_SMEM  ((68608 + 9216) * 2 + 1024)   // 156672 bytes
__global__ void __launch_bounds__(512)
mlp_kernel(const __half* __restrict__ x3h, const float* __restrict__ x,
           const __half* __restrict__ w1t, const __half* __restrict__ w2t,
           const __half* __restrict__ w3t,
           const float* __restrict__ u1, const float* __restrict__ u2,
           const float* __restrict__ cc,
           const float* __restrict__ fc2b, const float* __restrict__ fc3b,
           float* __restrict__ out, int n) {
    extern __shared__ __half sm[];
    __half* sH1 = sm;                       // [128][392]
    __half* sW  = sm + 50176;               // 2 x [128][72]
    __half* sA  = sm + 68608;               // [128][72]
    float*  sXR = (float*)(sm + 77824);     // [128][2]

    const int tid = threadIdx.x;
    const int warp = tid >> 5, lane = tid & 31;
    const int wm = warp >> 2, wn = warp & 3;    // 4m x 4n
    const int grp = lane >> 2, qid = lane & 3;
    const int row0 = blockIdx.x * 128;

    auto load_w = [&](int t, int b) {
        __half* dst = sW + b * FM_WSZ;
        if (t < 3) {
            const __half* src = w1t + (size_t)t * 128 * 64;
#pragma unroll
            for (int l = 0; l < 2; l++) {
                int i = tid + l * 512; int r = i >> 3, c8 = (i & 7) * 8;
                cp16(&dst[r * 72 + c8], src + r * 64 + c8, true);
            }
        } else if (t < 9) {
            int kk = (t - 3) * 64;
#pragma unroll
            for (int l = 0; l < 2; l++) {
                int i = tid + l * 512; int r = i >> 3, c8 = (i & 7) * 8;
                cp16(&dst[r * 72 + c8], w2t + (size_t)r * 384 + kk + c8, true);
            }
        } else {  // W3t: 64 rows x 128 k, stride 136
#pragma unroll
            for (int l = 0; l < 2; l++) {
                int i = tid + l * 512; int r = i >> 4, c8 = (i & 15) * 8;
                cp16(&dst[r * 136 + c8], w3t + (size_t)r * 128 + c8, true);
            }
        }
    };

#pragma unroll
    for (int l = 0; l < 2; l++) {
        int i = tid + l * 512; int r = i >> 3, c8 = (i & 7) * 8;
        bool v = row0 + r < n;
        cp16(&sA[r * 72 + c8], x3h + (size_t)(v ? row0 + r : 0) * 64 + c8, v);
    }
    if (tid < 128) {
        bool v = row0 + tid < n;
        cp8(&sXR[tid * 2], x + (size_t)(v ? row0 + tid : 0) * 130, v);
    }
    load_w(0, 0); CP_COMMIT();
    load_w(1, 1); CP_COMMIT();

    // ---- stage 1: fc1 (K=64), 3 output chunks of 128 cols -> sH1 fp16 ----
    for (int j = 0; j < 3; j++) {
        CP_WAIT1(); __syncthreads();
        const __half* Bt = sW + (j & 1) * FM_WSZ;
        float acc[2][4][4] = {};
#pragma unroll
        for (int ks = 0; ks < 4; ks++) {
            const int k0 = ks * 16;
            unsigned a[2][4], b[4][2];
#pragma unroll
            for (int mf = 0; mf < 2; mf++) {
                int r = wm * 32 + mf * 16 + grp;
                a[mf][0] = *(const unsigned*)&sA[r * 72 + k0 + 2 * qid];
                a[mf][1] = *(const unsigned*)&sA[(r + 8) * 72 + k0 + 2 * qid];
                a[mf][2] = *(const unsigned*)&sA[r * 72 + k0 + 2 * qid + 8];
                a[mf][3] = *(const unsigned*)&sA[(r + 8) * 72 + k0 + 2 * qid + 8];
            }
#pragma unroll
            for (int nf = 0; nf < 4; nf++) {
                int c = wn * 32 + nf * 8 + grp;
                b[nf][0] = *(const unsigned*)&Bt[c * 72 + k0 + 2 * qid];
                b[nf][1] = *(const unsigned*)&Bt[c * 72 + k0 + 2 * qid + 8];
            }
#pragma unroll
            for (int mf = 0; mf < 2; mf++)
#pragma unroll
                for (int nf = 0; nf < 4; nf++)
                    mma_f16(acc[mf][nf], a[mf], b[nf]);
        }
#pragma unroll
        for (int mf = 0; mf < 2; mf++)
#pragma unroll
            for (int hi = 0; hi < 2; hi++) {
                int rl = wm * 32 + mf * 16 + grp + hi * 8;
                float xa = sXR[rl * 2], xb = sXR[rl * 2 + 1];
#pragma unroll
                for (int nf = 0; nf < 4; nf++) {
                    int c = wn * 32 + nf * 8 + qid * 2;
                    int gc = j * 128 + c;
                    float v0 = acc[mf][nf][hi * 2 + 0] + xa * u1[gc] + xb * u2[gc] + cc[gc];
                    float v1 = acc[mf][nf][hi * 2 + 1] + xa * u1[gc + 1] + xb * u2[gc + 1] + cc[gc + 1];
                    v0 = fmaxf(v0, 0.f); v1 = fmaxf(v1, 0.f);
                    *(half2*)&sH1[rl * 392 + gc] = __floats2half2_rn(v0, v1);
                }
            }
        __syncthreads();
        load_w(j + 2, j & 1); CP_COMMIT();
    }

    // ---- stage 2: fc2 (K=384 from sH1) ----
    float acc2[2][4][4] = {};
    for (int kc = 0; kc < 6; kc++) {
        CP_WAIT1(); __syncthreads();
        const __half* Bt = sW + ((kc + 3) & 1) * FM_WSZ;
#pragma unroll
        for (int ks = 0; ks < 4; ks++) {
            const int k0 = kc * 64 + ks * 16;
            const int kb = ks * 16;
            unsigned a[2][4], b[4][2];
#pragma unroll
            for (int mf = 0; mf < 2; mf++) {
                int r = wm * 32 + mf * 16 + grp;
                a[mf][0] = *(const unsigned*)&sH1[r * 392 + k0 + 2 * qid];
                a[mf][1] = *(const unsigned*)&sH1[(r + 8) * 392 + k0 + 2 * qid];
                a[mf][2] = *(const unsigned*)&sH1[r * 392 + k0 + 2 * qid + 8];
                a[mf][3] = *(const unsigned*)&sH1[(r + 8) * 392 + k0 + 2 * qid + 8];
            }
#pragma unroll
            for (int nf = 0; nf < 4; nf++) {
                int c = wn * 32 + nf * 8 + grp;
                b[nf][0] = *(const unsigned*)&Bt[c * 72 + kb + 2 * qid];
                b[nf][1] = *(const unsigned*)&Bt[c * 72 + kb + 2 * qid + 8];
            }
#pragma unroll
            for (int mf = 0; mf < 2; mf++)
#pragma unroll
                for (int nf = 0; nf < 4; nf++)
                    mma_f16(acc2[mf][nf], a[mf], b[nf]);
        }
        __syncthreads();
        int t = kc + 5;
        if (t <= 9) { load_w(t, (kc + 3) & 1); CP_COMMIT(); }
    }

    // ---- stage 2 epilogue -> sH2 fp16 (reuses sH1) ----
    __half* sH2 = sH1;
#pragma unroll
    for (int mf = 0; mf < 2; mf++)
#pragma unroll
        for (int hi = 0; hi < 2; hi++) {
            int rl = wm * 32 + mf * 16 + grp + hi * 8;
#pragma unroll
            for (int nf = 0; nf < 4; nf++) {
                int c = wn * 32 + nf * 8 + qid * 2;
                float v0 = fmaxf(acc2[mf][nf][hi * 2 + 0] + fc2b[c], 0.f);
                float v1 = fmaxf(acc2[mf][nf][hi * 2 + 1] + fc2b[c + 1], 0.f);
                *(half2*)&sH2[rl * 136 + c] = __floats2half2_rn(v0, v1);
            }
        }
    CP_WAIT0(); __syncthreads();

    // ---- stage 3: fc3 (K=128 from sH2), warp tile 32x16 -> out fp32 ----
    {
        const __half* Bt = sW + 1 * FM_WSZ;
        float acc3[2][2][4] = {};
#pragma unroll
        for (int ks = 0; ks < 8; ks++) {
            const int k0 = ks * 16;
            unsigned a[2][4], b[2][2];
#pragma unroll
            for (int mf = 0; mf < 2; mf++) {
                int r = wm * 32 + mf * 16 + grp;
                a[mf][0] = *(const unsigned*)&sH2[r * 136 + k0 + 2 * qid];
                a[mf][1] = *(const unsigned*)&sH2[(r + 8) * 136 + k0 + 2 * qid];
                a[mf][2] = *(const unsigned*)&sH2[r * 136 + k0 + 2 * qid + 8];
                a[mf][3] = *(const unsigned*)&sH2[(r + 8) * 136 + k0 + 2 * qid + 8];
            }
#pragma unroll
            for (int nf = 0; nf < 2; nf++) {
                int c = wn * 16 + nf * 8 + grp;
                b[nf][0] = *(const unsigned*)&Bt[c * 136 + k0 + 2 * qid];
                b[nf][1] = *(const unsigned*)&Bt[c * 136 + k0 + 2 * qid + 8];
            }
#pragma unroll
            for (int mf = 0; mf < 2; mf++)
#pragma unroll
                for (int nf = 0; nf < 2; nf++)
                    mma_f16(acc3[mf][nf], a[mf], b[nf]);
        }
#pragma unroll
        for (int mf = 0; mf < 2; mf++)
#pragma unroll
            for (int hi = 0; hi < 2; hi++) {
                int r = row0 + wm * 32 + mf * 16 + grp + hi * 8;
                if (r >= n) continue;
#pragma unroll
                for (int nf = 0; nf < 2; nf++) {
                    int c = wn * 16 + nf * 8 + qid * 2;
                    float v0 = acc3[mf][nf][hi * 2 + 0] + fc3b[c];
                    float v1 = acc3[mf][nf][hi * 2 + 1] + fc3b[c + 1];
                    *(float2*)&out[(size_t)r * 64 + c] = make_float2(v0, v1);
                }
            }
    }
}

// ---------------- h GEMM: split 3xTF32, fused alpha + fp16 write --------------
#define TS_ASZ (128 * 36)
#define TS_BSZ (32 * 72)
#define TS_SMEM ((2 * (TS_ASZ + TS_BSZ)) * 4)
__global__ void __launch_bounds__(128)
h_gemm(const float* __restrict__ A, int lda,
       const float* __restrict__ W, int ldw,
       const float* __restrict__ asrc, const float* __restrict__ adst,
       int n) {
    constexpr int BM = 128, BK = 32;
    extern __shared__ float smem[];
    float* Asf = smem;
    float* Bsf = smem + 2 * TS_ASZ;

    const int tid = threadIdx.x;
    const int warp = tid >> 5, lane = tid & 31;
    const int wm = warp >> 1;
    const int wn = warp & 1;
    const int grp = lane >> 2, qid = lane & 3;
    const int row0 = blockIdx.x * BM;
    const int nk = 128 / BK;   // K = 128

    float acc[4][4][4] = {};

    auto load_tile = [&](int s, int kk) {
        float* At = Asf + s * TS_ASZ;
        float* Bt = Bsf + s * TS_BSZ;
#pragma unroll
        for (int l = 0; l < 16; l++) {
            int i = tid + l * 128;
            int r = i >> 4, c2 = (i & 15) * 2;
            int gr = row0 + r;
            bool v = gr < n;
            cp8(&At[r * 36 + c2], A + (size_t)(v ? gr : n - 1) * lda + kk + c2, v);
        }
#pragma unroll
        for (int l = 0; l < 4; l++) {
            int i = tid + l * 128;
            int r = i >> 4, c4 = (i & 15) * 4;
            cp16(&Bt[r * 72 + c4], &W[(size_t)(kk + r) * ldw + c4], true);
        }
        CP_COMMIT();
    };

    load_tile(0, 0);
    for (int t = 0; t < nk; t++) {
        if (t + 1 < nk) load_tile((t + 1) & 1, (t + 1) * BK);
        if (t + 1 < nk) CP_WAIT1(); else CP_WAIT0();
        __syncthreads();
        const float* At = Asf + (t & 1) * TS_ASZ;
        const float* Bt = Bsf + (t & 1) * TS_BSZ;
#pragma unroll
        for (int ks = 0; ks < BK / 8; ks++) {
            const int k0 = ks * 8;
            unsigned ah[4][4], al[4][4], bh[4][2], bl[4][2];
#pragma unroll
            for (int mf = 0; mf < 4; mf++) {
                int r = wm * 64 + mf * 16 + grp;
                float x0 = At[r * 36 + k0 + qid];
                float x1 = At[(r + 8) * 36 + k0 + qid];
                float x2 = At[r * 36 + k0 + qid + 4];
                float x3 = At[(r + 8) * 36 + k0 + qid + 4];
                ah[mf][0] = f2tf(x0); al[mf][0] = f2tf(x0 - __uint_as_float(ah[mf][0]));
                ah[mf][1] = f2tf(x1); al[mf][1] = f2tf(x1 - __uint_as_float(ah[mf][1]));
                ah[mf][2] = f2tf(x2); al[mf][2] = f2tf(x2 - __uint_as_float(ah[mf][2]));
                ah[mf][3] = f2tf(x3); al[mf][3] = f2tf(x3 - __uint_as_float(ah[mf][3]));
            }
#pragma unroll
            for (int nf = 0; nf < 4; nf++) {
                int c = wn * 32 + nf * 8 + grp;
                float y0 = Bt[(k0 + qid) * 72 + c];
                float y1 = Bt[(k0 + qid + 4) * 72 + c];
                bh[nf][0] = f2tf(y0); bl[nf][0] = f2tf(y0 - __uint_as_float(bh[nf][0]));
                bh[nf][1] = f2tf(y1); bl[nf][1] = f2tf(y1 - __uint_as_float(bh[nf][1]));
            }
#pragma unroll
            for (int mf = 0; mf < 4; mf++)
#pragma unroll
                for (int nf = 0; nf < 4; nf++) {
                    mma_tf32(acc[mf][nf], al[mf], bh[nf]);
                    mma_tf32(acc[mf][nf], ah[mf], bl[nf]);
                    mma_tf32(acc[mf][nf], ah[mf], bh[nf]);
                }
        }
        __syncthreads();
    }

    // epilogue: fp16 h write + alpha partial dots (quad reduce -> atomics)
#pragma unroll
    for (int mf = 0; mf < 4; mf++) {
#pragma unroll
        for (int hi = 0; hi < 2; hi++) {
            int r = row0 + wm * 64 + mf * 16 + grp + hi * 8;
            bool valid = r < n;
            float sp = 0.f, dp = 0.f;
#pragma unroll
            for (int nf = 0; nf < 4; nf++) {
                int c = wn * 32 + nf * 8 + qid * 2;
                float v0 = acc[mf][nf][hi * 2 + 0];
                float v1 = acc[mf][nf][hi * 2 + 1];
                if (valid)
                    *(half2*)&g_hh[(size_t)r * 64 + c] = __floats2half2_rn(v0, v1);
                sp += v0 * asrc[c] + v1 * asrc[c + 1];
                dp += v0 * adst[c] + v1 * adst[c + 1];
            }
            sp += __shfl_xor_sync(0xffffffffu, sp, 1);
            sp += __shfl_xor_sync(0xffffffffu, sp, 2);
            dp += __shfl_xor_sync(0xffffffffu, dp, 1);
            dp += __shfl_xor_sync(0xffffffffu, dp, 2);
            if (valid && qid == 0) {
                atomicAdd(&g_as[r], sp);
                atomicAdd(&g_ad[r], dp);
            }
        }
    }
}

// -----------------------------------------------------------------------------
extern "C" void kernel_launch(void* const* d_in, const int* in_sizes, int n_in,
                              void* d_out, int out_size) {
    const float* x    = (const float*)d_in[0];
    const void*  ei   = d_in[1];
    const float* w1   = (const float*)d_in[2];
    const float* b1   = (const float*)d_in[3];
    const float* w2   = (const float*)d_in[4];
    const float* b2   = (const float*)d_in[5];
    const float* gatw = (const float*)d_in[6];
    const float* asrc = (const float*)d_in[7];
    const float* adst = (const float*)d_in[8];
    const float* gatb = (const float*)d_in[9];
    const float* fc1w = (const float*)d_in[10];
    const float* fc1b = (const float*)d_in[11];
    const float* fc2w = (const float*)d_in[12];
    const float* fc2b = (const float*)d_in[13];
    const float* fc3w = (const float*)d_in[14];
    const float* fc3b = (const float*)d_in[15];
    float* out = (float*)d_out;

    void *px3h, *pu1, *pu2, *pcc, *pw1t, *pw2t, *pw3t;
    cudaGetSymbolAddress(&px3h, g_x3h);
    cudaGetSymbolAddress(&pu1,  g_u1);
    cudaGetSymbolAddress(&pu2,  g_u2);
    cudaGetSymbolAddress(&pcc,  g_cc);
    cudaGetSymbolAddress(&pw1t, g_w1t);
    cudaGetSymbolAddress(&pw2t, g_w2t);
    cudaGetSymbolAddress(&pw3t, g_w3t);

    static cudaStream_t s2 = nullptr;
    static cudaEvent_t evFork = nullptr, evJoin = nullptr;
    if (!s2) {   // first call = correctness run (not captured): safe to create
        cudaStreamCreateWithFlags(&s2, cudaStreamNonBlocking);
        cudaEventCreateWithFlags(&evFork, cudaEventDisableTiming);
        cudaEventCreateWithFlags(&evJoin, cudaEventDisableTiming);
        cudaFuncSetAttribute(mlp_kernel, cudaFuncAttributeMaxDynamicSharedMemorySize, FM_SMEM);
        cudaFuncSetAttribute(h_gemm,     cudaFuncAttributeMaxDynamicSharedMemorySize, TS_SMEM);
    }

    const int GX = (NN + 127) / 128;   // 782

    // fused setup (stream 0): zero cnt/as/ad/dsum + detect + prep + transposes
    setup_kernel<<<NZB + 3 + 192, 256>>>((const unsigned*)ei,
                                         w1, b1, w2, b2, gatb, fc1w, fc1b, fc2w, fc3w);

    // fork: CSR build on s2 concurrent with h GEMM on stream 0
    cudaEventRecord(evFork, 0);
    cudaStreamWaitEvent(s2, evFork, 0);
    hist_kernel<<<(EE + 255) / 256, 256, 0, s2>>>(ei);
    scan1_kernel<<<NSB, 256, 0, s2>>>();
    scan2_kernel<<<1, 256, 0, s2>>>();
    scan3_kernel<<<NSB, 512, 0, s2>>>();
    cudaEventRecord(evJoin, s2);

    // stream 0: h GEMM with fused alpha + fp16 h
    h_gemm<<<GX, 128, TS_SMEM>>>(x + 2, 130, gatw, 64, asrc, adst, NN);

    // join, then edge softmax + aggregation + fused MLP
    cudaStreamWaitEvent(0, evJoin, 0);
    scatter_kernel<<<(EE + 255) / 256, 256>>>(ei);
    agg_kernel<<<(NN * 32 + 255) / 256, 256>>>();
    mlp_kernel<<<GX, 512, FM_SMEM>>>((const __half*)px3h, x,
                                     (const __half*)pw1t, (const __half*)pw2t,
                                     (const __half*)pw3t,
                                     (const float*)pu1, (const float*)pu2,
                                     (const float*)pcc,
                                     fc2b, fc3b, out, NN);
}

// round 15
// speedup vs baseline: 1.0912x; 1.0912x over previous
#include <cuda_runtime.h>
#include <cuda_fp16.h>
#include <math.h>

#define NN 100000
#define EE 1600000
#define NSB ((NN + 511) / 512)   // 196 scan blocks
#define NZB ((NN + 255) / 256)   // 391 zero blocks

// ---------------- scratch (device globals; no allocation allowed) ------------
__device__ __half g_hh [(size_t)NN * 64];    // GAT h (fp16, for agg gather)
__device__ __half g_x3h[(size_t)NN * 64];    // aggregated GAT output (fp16)
__device__ float  g_as [NN];
__device__ float  g_ad [NN];
__device__ int    g_cnt[NN];                 // in-degree
__device__ int    g_off[NN];                 // CSR row offsets
__device__ int    g_pos[NN];                 // scatter cursors
__device__ float2 g_edge[EE];                // CSR (src bit-cast, exp) pairs
__device__ int    g_bsum[NSB], g_boff[NSB];
__device__ float  g_u1[384], g_u2[384], g_cc[384];
__device__ __half g_w1t[384 * 64];           // fc1_w[128:192,:]^T fp16 [n][k]
__device__ __half g_w2t[128 * 384];          // fc2_w^T fp16            [n][k]
__device__ __half g_w3t[64 * 128];           // fc3_w^T fp16            [n][k]
__device__ int    g_is64;

// ---------------- fused setup: zero / detect / prep / transpose --------------
__global__ void setup_kernel(const unsigned* __restrict__ p,
                             const float* __restrict__ w1, const float* __restrict__ b1,
                             const float* __restrict__ w2, const float* __restrict__ b2,
                             const float* __restrict__ gatb,
                             const float* __restrict__ fc1w, const float* __restrict__ fc1b,
                             const float* __restrict__ fc2w, const float* __restrict__ fc3w) {
    __shared__ unsigned sh[256];
    int b = blockIdx.x, t = threadIdx.x;
    if (b < NZB) {
        int i = b * 256 + t;
        if (i < NN) g_cnt[i] = 0;
        return;
    }
    if (b == NZB) {   // int64 detection: high words all zero => int64
        sh[t] = p[2 * t + 1];
        __syncthreads();
        if (t == 0) {
            unsigned o = 0;
            for (int i = 0; i < 256; i++) o |= sh[i];
            g_is64 = (o == 0) ? 1 : 0;
        }
        return;
    }
    if (b <= NZB + 2) {  // prep: rank-2 epilogue vectors (192 cols per block)
        if (t < 192) {
            int k = (b - (NZB + 1)) * 192 + t;
            float s1 = 0.f, s2 = 0.f, c = fc1b[k];
            for (int j = 0; j < 64; j++) {
                float wa = fc1w[(size_t)j * 384 + k];
                float wb = fc1w[(size_t)(64 + j) * 384 + k];
                float wc = fc1w[(size_t)(128 + j) * 384 + k];
                s1 += w1[j] * wa;
                s2 += w2[j] * wb;
                c  += b1[j] * wa + b2[j] * wb + gatb[j] * wc;
            }
            g_u1[k] = s1; g_u2[k] = s2; g_cc[k] = c;
        }
        return;
    }
    // weight transpose + fp16 cast
    int i = (b - (NZB + 3)) * 256 + t;
    if (i < 384 * 64) {                       // g_w1t[c][k] = fc1w[128+k][c]
        int c = i >> 6, k = i & 63;
        g_w1t[i] = __float2half_rn(fc1w[(size_t)(128 + k) * 384 + c]);
    }
    if (i < 128 * 384) {                      // g_w2t[c][k] = fc2w[k][c]
        int c = i / 384, k = i % 384;
        g_w2t[i] = __float2half_rn(fc2w[(size_t)k * 128 + c]);
    }
    if (i < 64 * 128) {                       // g_w3t[c][k] = fc3w[k][c]
        int c = i >> 7, k = i & 127;
        g_w3t[i] = __float2half_rn(fc3w[(size_t)k * 64 + c]);
    }
}

// ---------------- degree histogram -------------------------------------------
__global__ void hist_kernel(const void* __restrict__ idx) {
    int e = blockIdx.x * blockDim.x + threadIdx.x;
    if (e >= EE) return;
    int d = g_is64 ? (int)((const long long*)idx)[EE + e]
                   : ((const int*)idx)[EE + e];
    atomicAdd(&g_cnt[d], 1);
}

// ---------------- 3-kernel exclusive scan over g_cnt -------------------------
__global__ void scan1_kernel() {
    __shared__ int sh[256];
    int b = blockIdx.x, t = threadIdx.x;
    int i0 = b * 512 + t;
    int v = 0;
    if (i0 < NN) v += g_cnt[i0];
    if (i0 + 256 < NN) v += g_cnt[i0 + 256];
    sh[t] = v; __syncthreads();
    for (int o = 128; o; o >>= 1) { if (t < o) sh[t] += sh[t + o]; __syncthreads(); }
    if (t == 0) g_bsum[b] = sh[0];
}

__global__ void scan2_kernel() {
    __shared__ int sh[256];
    int t = threadIdx.x;
    int v = (t < NSB) ? g_bsum[t] : 0;
    sh[t] = v;
    for (int o = 1; o < 256; o <<= 1) {
        __syncthreads();
        int u = (t >= o) ? sh[t - o] : 0;
        __syncthreads();
        sh[t] += u;
    }
    __syncthreads();
    if (t < NSB) g_boff[t] = sh[t] - v;
}

__global__ void scan3_kernel() {
    __shared__ int sh[512];
    int b = blockIdx.x, t = threadIdx.x;
    int i = b * 512 + t;
    int c = (i < NN) ? g_cnt[i] : 0;
    sh[t] = c;
    for (int o = 1; o < 512; o <<= 1) {
        __syncthreads();
        int u = (t >= o) ? sh[t - o] : 0;
        __syncthreads();
        sh[t] += u;
    }
    __syncthreads();
    if (i < NN) {
        int excl = sh[t] - c + g_boff[b];
        g_off[i] = excl;
        g_pos[i] = excl;
    }
}

// ---------------- scatter into CSR: packed (src, exp) ------------------------
__global__ void scatter_kernel(const void* __restrict__ idx) {
    int e = blockIdx.x * blockDim.x + threadIdx.x;
    if (e >= EE) return;
    int s, d;
    if (g_is64) {
        const long long* q = (const long long*)idx;
        s = (int)q[e]; d = (int)q[EE + e];
    } else {
        const int* q = (const int*)idx;
        s = q[e]; d = q[EE + e];
    }
    float v = g_as[s] + g_ad[d];
    v = (v > 0.f) ? v : 0.2f * v;
    float ex = expf(v);
    int p = atomicAdd(&g_pos[d], 1);
    g_edge[p] = make_float2(__int_as_float(s), ex);
}

// ---------------- CSR aggregation: warp per node, fp16 gather ----------------
__global__ void agg_kernel() {
    int node = (int)((blockIdx.x * (size_t)blockDim.x + threadIdx.x) >> 5);
    int lane = threadIdx.x & 31;
    if (node >= NN) return;
    int beg = g_off[node];
    int cnt = g_cnt[node];
    float v = g_as[node] + g_ad[node];
    v = (v > 0.f) ? v : 0.2f * v;
    float ex_self = expf(v);
    // denominator from precomputed contiguous ex stream
    float dsum = 0.f;
    for (int i = lane; i < cnt; i += 32) dsum += g_edge[beg + i].y;
#pragma unroll
    for (int o = 16; o; o >>= 1) dsum += __shfl_xor_sync(0xffffffffu, dsum, o);
    float invd = 1.f / (dsum + ex_self + 1e-16f);
    float2 acc;
    {
        half2 hv = *(const half2*)(g_hh + (size_t)node * 64 + lane * 2);
        float2 f = __half22float2(hv);
        float c = ex_self * invd;
        acc.x = c * f.x; acc.y = c * f.y;
    }
#pragma unroll 4
    for (int e = 0; e < cnt; e++) {
        float2 ev = g_edge[beg + e];
        int s = __float_as_int(ev.x);
        float c = ev.y * invd;
        half2 hv = *(const half2*)(g_hh + (size_t)s * 64 + lane * 2);
        float2 f = __half22float2(hv);
        acc.x += c * f.x; acc.y += c * f.y;
    }
    *(half2*)(g_x3h + (size_t)node * 64 + lane * 2) = __floats2half2_rn(acc.x, acc.y);
}

// ---------------- TF32 / fp16 / cp.async helpers -------------------------------
__device__ __forceinline__ unsigned f2tf(float x) {
    unsigned r; asm("cvt.rna.tf32.f32 %0, %1;" : "=r"(r) : "f"(x)); return r;
}
__device__ __forceinline__ void mma_tf32(float* d, const unsigned* a, const unsigned* b) {
    asm volatile(
        "mma.sync.aligned.m16n8k8.row.col.f32.tf32.tf32.f32 "
        "{%0,%1,%2,%3}, {%4,%5,%6,%7}, {%8,%9}, {%0,%1,%2,%3};\n"
        : "+f"(d[0]), "+f"(d[1]), "+f"(d[2]), "+f"(d[3])
        : "r"(a[0]), "r"(a[1]), "r"(a[2]), "r"(a[3]), "r"(b[0]), "r"(b[1]));
}
__device__ __forceinline__ void mma_f16(float* d, const unsigned* a, const unsigned* b) {
    asm volatile(
        "mma.sync.aligned.m16n8k16.row.col.f32.f16.f16.f32 "
        "{%0,%1,%2,%3}, {%4,%5,%6,%7}, {%8,%9}, {%0,%1,%2,%3};\n"
        : "+f"(d[0]), "+f"(d[1]), "+f"(d[2]), "+f"(d[3])
        : "r"(a[0]), "r"(a[1]), "r"(a[2]), "r"(a[3]), "r"(b[0]), "r"(b[1]));
}
__device__ __forceinline__ void cp16(void* smem, const void* g, bool valid) {
    unsigned sa = (unsigned)__cvta_generic_to_shared(smem);
    int sz = valid ? 16 : 0;
    asm volatile("cp.async.cg.shared.global [%0], [%1], 16, %2;" :: "r"(sa), "l"(g), "r"(sz));
}
__device__ __forceinline__ void cp8(void* smem, const void* g, bool valid) {
    unsigned sa = (unsigned)__cvta_generic_to_shared(smem);
    int sz = valid ? 8 : 0;
    asm volatile("cp.async.ca.shared.global [%0], [%1], 8, %2;" :: "r"(sa), "l"(g), "r"(sz));
}
#define CP_COMMIT() asm volatile("cp.async.commit_group;")
#define CP_WAIT1()  asm volatile("cp.async.wait_group 1;")
#define CP_WAIT0()  asm volatile("cp.async.wait_group 0;")

// ---------------- fused MLP: fc1 -> fc2 -> fc3, 256 threads (R13 config) ------
#define FM_WSZ   (128 * 72)
#define FM_SMEM  ((68608 + 9216) * 2 + 1024)   // 156672 bytes
__global__ void __launch_bounds__(256)
mlp_kernel(const __half* __restrict__ x3h, const float* __restrict__ x,
           const __half* __restrict__ w1t, const __half* __restrict__ w2t,
           const __half* __restrict__ w3t,
           const float* __restrict__ u1, const float* __restrict__ u2,
           const float* __restrict__ cc,
           const float* __restrict__ fc2b, const float* __restrict__ fc3b,
           float* __restrict__ out, int n) {
    extern __shared__ __half sm[];
    __half* sH1 = sm;                       // [128][392]
    __half* sW  = sm + 50176;               // 2 x [128][72]
    __half* sA  = sm + 68608;               // [128][72]
    float*  sXR = (float*)(sm + 77824);     // [128][2]

    const int tid = threadIdx.x;
    const int warp = tid >> 5, lane = tid & 31;
    const int wm = warp >> 2, wn = warp & 3;
    const int grp = lane >> 2, qid = lane & 3;
    const int row0 = blockIdx.x * 128;

    auto load_w = [&](int t, int b) {
        __half* dst = sW + b * FM_WSZ;
        if (t < 3) {
            const __half* src = w1t + (size_t)t * 128 * 64;
#pragma unroll
            for (int l = 0; l < 4; l++) {
                int i = tid + l * 256; int r = i >> 3, c8 = (i & 7) * 8;
                cp16(&dst[r * 72 + c8], src + r * 64 + c8, true);
            }
        } else if (t < 9) {
            int kk = (t - 3) * 64;
#pragma unroll
            for (int l = 0; l < 4; l++) {
                int i = tid + l * 256; int r = i >> 3, c8 = (i & 7) * 8;
                cp16(&dst[r * 72 + c8], w2t + (size_t)r * 384 + kk + c8, true);
            }
        } else {
#pragma unroll
            for (int l = 0; l < 4; l++) {
                int i = tid + l * 256; int r = i >> 4, c8 = (i & 15) * 8;
                cp16(&dst[r * 136 + c8], w3t + (size_t)r * 128 + c8, true);
            }
        }
    };

#pragma unroll
    for (int l = 0; l < 4; l++) {
        int i = tid + l * 256; int r = i >> 3, c8 = (i & 7) * 8;
        bool v = row0 + r < n;
        cp16(&sA[r * 72 + c8], x3h + (size_t)(v ? row0 + r : 0) * 64 + c8, v);
    }
    if (tid < 128) {
        bool v = row0 + tid < n;
        cp8(&sXR[tid * 2], x + (size_t)(v ? row0 + tid : 0) * 130, v);
    }
    load_w(0, 0); CP_COMMIT();
    load_w(1, 1); CP_COMMIT();

    // ---- stage 1: fc1 (K=64), 3 output chunks of 128 cols -> sH1 fp16 ----
    for (int j = 0; j < 3; j++) {
        CP_WAIT1(); __syncthreads();
        const __half* Bt = sW + (j & 1) * FM_WSZ;
        float acc[4][4][4] = {};
#pragma unroll
        for (int ks = 0; ks < 4; ks++) {
            const int k0 = ks * 16;
            unsigned a[4][4], b[4][2];
#pragma unroll
            for (int mf = 0; mf < 4; mf++) {
                int r = wm * 64 + mf * 16 + grp;
                a[mf][0] = *(const unsigned*)&sA[r * 72 + k0 + 2 * qid];
                a[mf][1] = *(const unsigned*)&sA[(r + 8) * 72 + k0 + 2 * qid];
                a[mf][2] = *(const unsigned*)&sA[r * 72 + k0 + 2 * qid + 8];
                a[mf][3] = *(const unsigned*)&sA[(r + 8) * 72 + k0 + 2 * qid + 8];
            }
#pragma unroll
            for (int nf = 0; nf < 4; nf++) {
                int c = wn * 32 + nf * 8 + grp;
                b[nf][0] = *(const unsigned*)&Bt[c * 72 + k0 + 2 * qid];
                b[nf][1] = *(const unsigned*)&Bt[c * 72 + k0 + 2 * qid + 8];
            }
#pragma unroll
            for (int mf = 0; mf < 4; mf++)
#pragma unroll
                for (int nf = 0; nf < 4; nf++)
                    mma_f16(acc[mf][nf], a[mf], b[nf]);
        }
#pragma unroll
        for (int mf = 0; mf < 4; mf++)
#pragma unroll
            for (int hi = 0; hi < 2; hi++) {
                int rl = wm * 64 + mf * 16 + grp + hi * 8;
                float xa = sXR[rl * 2], xb = sXR[rl * 2 + 1];
#pragma unroll
                for (int nf = 0; nf < 4; nf++) {
                    int c = wn * 32 + nf * 8 + qid * 2;
                    int gc = j * 128 + c;
                    float v0 = acc[mf][nf][hi * 2 + 0] + xa * u1[gc] + xb * u2[gc] + cc[gc];
                    float v1 = acc[mf][nf][hi * 2 + 1] + xa * u1[gc + 1] + xb * u2[gc + 1] + cc[gc + 1];
                    v0 = fmaxf(v0, 0.f); v1 = fmaxf(v1, 0.f);
                    *(half2*)&sH1[rl * 392 + gc] = __floats2half2_rn(v0, v1);
                }
            }
        __syncthreads();
        load_w(j + 2, j & 1); CP_COMMIT();
    }

    // ---- stage 2: fc2 (K=384 from sH1) ----
    float acc2[4][4][4] = {};
    for (int kc = 0; kc < 6; kc++) {
        CP_WAIT1(); __syncthreads();
        const __half* Bt = sW + ((kc + 3) & 1) * FM_WSZ;
#pragma unroll
        for (int ks = 0; ks < 4; ks++) {
            const int k0 = kc * 64 + ks * 16;
            const int kb = ks * 16;
            unsigned a[4][4], b[4][2];
#pragma unroll
            for (int mf = 0; mf < 4; mf++) {
                int r = wm * 64 + mf * 16 + grp;
                a[mf][0] = *(const unsigned*)&sH1[r * 392 + k0 + 2 * qid];
                a[mf][1] = *(const unsigned*)&sH1[(r + 8) * 392 + k0 + 2 * qid];
                a[mf][2] = *(const unsigned*)&sH1[r * 392 + k0 + 2 * qid + 8];
                a[mf][3] = *(const unsigned*)&sH1[(r + 8) * 392 + k0 + 2 * qid + 8];
            }
#pragma unroll
            for (int nf = 0; nf < 4; nf++) {
                int c = wn * 32 + nf * 8 + grp;
                b[nf][0] = *(const unsigned*)&Bt[c * 72 + kb + 2 * qid];
                b[nf][1] = *(const unsigned*)&Bt[c * 72 + kb + 2 * qid + 8];
            }
#pragma unroll
            for (int mf = 0; mf < 4; mf++)
#pragma unroll
                for (int nf = 0; nf < 4; nf++)
                    mma_f16(acc2[mf][nf], a[mf], b[nf]);
        }
        __syncthreads();
        int t = kc + 5;
        if (t <= 9) { load_w(t, (kc + 3) & 1); CP_COMMIT(); }
    }

    // ---- stage 2 epilogue -> sH2 fp16 (reuses sH1) ----
    __half* sH2 = sH1;
#pragma unroll
    for (int mf = 0; mf < 4; mf++)
#pragma unroll
        for (int hi = 0; hi < 2; hi++) {
            int rl = wm * 64 + mf * 16 + grp + hi * 8;
#pragma unroll
            for (int nf = 0; nf < 4; nf++) {
                int c = wn * 32 + nf * 8 + qid * 2;
                float v0 = fmaxf(acc2[mf][nf][hi * 2 + 0] + fc2b[c], 0.f);
                float v1 = fmaxf(acc2[mf][nf][hi * 2 + 1] + fc2b[c + 1], 0.f);
                *(half2*)&sH2[rl * 136 + c] = __floats2half2_rn(v0, v1);
            }
        }
    CP_WAIT0(); __syncthreads();

    // ---- stage 3: fc3 (K=128 from sH2) -> out fp32 ----
    {
        const __half* Bt = sW + 1 * FM_WSZ;
        float acc3[4][2][4] = {};
#pragma unroll
        for (int ks = 0; ks < 8; ks++) {
            const int k0 = ks * 16;
            unsigned a[4][4], b[2][2];
#pragma unroll
            for (int mf = 0; mf < 4; mf++) {
                int r = wm * 64 + mf * 16 + grp;
                a[mf][0] = *(const unsigned*)&sH2[r * 136 + k0 + 2 * qid];
                a[mf][1] = *(const unsigned*)&sH2[(r + 8) * 136 + k0 + 2 * qid];
                a[mf][2] = *(const unsigned*)&sH2[r * 136 + k0 + 2 * qid + 8];
                a[mf][3] = *(const unsigned*)&sH2[(r + 8) * 136 + k0 + 2 * qid + 8];
            }
#pragma unroll
            for (int nf = 0; nf < 2; nf++) {
                int c = wn * 16 + nf * 8 + grp;
                b[nf][0] = *(const unsigned*)&Bt[c * 136 + k0 + 2 * qid];
                b[nf][1] = *(const unsigned*)&Bt[c * 136 + k0 + 2 * qid + 8];
            }
#pragma unroll
            for (int mf = 0; mf < 4; mf++)
#pragma unroll
                for (int nf = 0; nf < 2; nf++)
                    mma_f16(acc3[mf][nf], a[mf], b[nf]);
        }
#pragma unroll
        for (int mf = 0; mf < 4; mf++)
#pragma unroll
            for (int hi = 0; hi < 2; hi++) {
                int r = row0 + wm * 64 + mf * 16 + grp + hi * 8;
                if (r >= n) continue;
#pragma unroll
                for (int nf = 0; nf < 2; nf++) {
                    int c = wn * 16 + nf * 8 + qid * 2;
                    float v0 = acc3[mf][nf][hi * 2 + 0] + fc3b[c];
                    float v1 = acc3[mf][nf][hi * 2 + 1] + fc3b[c + 1];
                    *(float2*)&out[(size_t)r * 64 + c] = make_float2(v0, v1);
                }
            }
    }
}

// ---------------- h GEMM: split 3xTF32, fused alpha (smem reduce) -------------
// h = x[:,2:130] @ gat_w (fp32 accum); epilogue: g_hh fp16 + g_as/g_ad stores.
#define TS_ASZ (128 * 36)
#define TS_BSZ (32 * 72)
#define TS_RED (2 * 2 * 128)                   // [wn][as/ad][row]
#define TS_SMEM (((2 * (TS_ASZ + TS_BSZ)) + TS_RED) * 4)
__global__ void __launch_bounds__(128)
h_gemm(const float* __restrict__ A, int lda,
       const float* __restrict__ W, int ldw,
       const float* __restrict__ asrc, const float* __restrict__ adst,
       int n) {
    constexpr int BM = 128, BK = 32;
    extern __shared__ float smem[];
    float* Asf = smem;
    float* Bsf = smem + 2 * TS_ASZ;
    float* sRed = smem + 2 * (TS_ASZ + TS_BSZ);   // [2][2][128]

    const int tid = threadIdx.x;
    const int warp = tid >> 5, lane = tid & 31;
    const int wm = warp >> 1;
    const int wn = warp & 1;
    const int grp = lane >> 2, qid = lane & 3;
    const int row0 = blockIdx.x * BM;
    const int nk = 128 / BK;   // K = 128

    float acc[4][4][4] = {};

    auto load_tile = [&](int s, int kk) {
        float* At = Asf + s * TS_ASZ;
        float* Bt = Bsf + s * TS_BSZ;
#pragma unroll
        for (int l = 0; l < 16; l++) {
            int i = tid + l * 128;
            int r = i >> 4, c2 = (i & 15) * 2;
            int gr = row0 + r;
            bool v = gr < n;
            cp8(&At[r * 36 + c2], A + (size_t)(v ? gr : n - 1) * lda + kk + c2, v);
        }
#pragma unroll
        for (int l = 0; l < 4; l++) {
            int i = tid + l * 128;
            int r = i >> 4, c4 = (i & 15) * 4;
            cp16(&Bt[r * 72 + c4], &W[(size_t)(kk + r) * ldw + c4], true);
        }
        CP_COMMIT();
    };

    load_tile(0, 0);
    for (int t = 0; t < nk; t++) {
        if (t + 1 < nk) load_tile((t + 1) & 1, (t + 1) * BK);
        if (t + 1 < nk) CP_WAIT1(); else CP_WAIT0();
        __syncthreads();
        const float* At = Asf + (t & 1) * TS_ASZ;
        const float* Bt = Bsf + (t & 1) * TS_BSZ;
#pragma unroll
        for (int ks = 0; ks < BK / 8; ks++) {
            const int k0 = ks * 8;
            unsigned ah[4][4], al[4][4], bh[4][2], bl[4][2];
#pragma unroll
            for (int mf = 0; mf < 4; mf++) {
                int r = wm * 64 + mf * 16 + grp;
                float x0 = At[r * 36 + k0 + qid];
                float x1 = At[(r + 8) * 36 + k0 + qid];
                float x2 = At[r * 36 + k0 + qid + 4];
                float x3 = At[(r + 8) * 36 + k0 + qid + 4];
                ah[mf][0] = f2tf(x0); al[mf][0] = f2tf(x0 - __uint_as_float(ah[mf][0]));
                ah[mf][1] = f2tf(x1); al[mf][1] = f2tf(x1 - __uint_as_float(ah[mf][1]));
                ah[mf][2] = f2tf(x2); al[mf][2] = f2tf(x2 - __uint_as_float(ah[mf][2]));
                ah[mf][3] = f2tf(x3); al[mf][3] = f2tf(x3 - __uint_as_float(ah[mf][3]));
            }
#pragma unroll
            for (int nf = 0; nf < 4; nf++) {
                int c = wn * 32 + nf * 8 + grp;
                float y0 = Bt[(k0 + qid) * 72 + c];
                float y1 = Bt[(k0 + qid + 4) * 72 + c];
                bh[nf][0] = f2tf(y0); bl[nf][0] = f2tf(y0 - __uint_as_float(bh[nf][0]));
                bh[nf][1] = f2tf(y1); bl[nf][1] = f2tf(y1 - __uint_as_float(bh[nf][1]));
            }
#pragma unroll
            for (int mf = 0; mf < 4; mf++)
#pragma unroll
                for (int nf = 0; nf < 4; nf++) {
                    mma_tf32(acc[mf][nf], al[mf], bh[nf]);
                    mma_tf32(acc[mf][nf], ah[mf], bl[nf]);
                    mma_tf32(acc[mf][nf], ah[mf], bh[nf]);
                }
        }
        __syncthreads();
    }

    // epilogue: fp16 h write + alpha partial dots -> smem reduce -> stores
#pragma unroll
    for (int mf = 0; mf < 4; mf++) {
#pragma unroll
        for (int hi = 0; hi < 2; hi++) {
            int rl = wm * 64 + mf * 16 + grp + hi * 8;   // block-local row
            int r = row0 + rl;
            bool valid = r < n;
            float sp = 0.f, dp = 0.f;
#pragma unroll
            for (int nf = 0; nf < 4; nf++) {
                int c = wn * 32 + nf * 8 + qid * 2;
                float v0 = acc[mf][nf][hi * 2 + 0];
                float v1 = acc[mf][nf][hi * 2 + 1];
                if (valid)
                    *(half2*)&g_hh[(size_t)r * 64 + c] = __floats2half2_rn(v0, v1);
                sp += v0 * asrc[c] + v1 * asrc[c + 1];
                dp += v0 * adst[c] + v1 * adst[c + 1];
            }
            sp += __shfl_xor_sync(0xffffffffu, sp, 1);
            sp += __shfl_xor_sync(0xffffffffu, sp, 2);
            dp += __shfl_xor_sync(0xffffffffu, dp, 1);
            dp += __shfl_xor_sync(0xffffffffu, dp, 2);
            if (qid == 0) {
                sRed[(wn * 2 + 0) * 128 + rl] = sp;
                sRed[(wn * 2 + 1) * 128 + rl] = dp;
            }
        }
    }
    __syncthreads();
    if (tid < 128) {
        int r = row0 + tid;
        if (r < n) {
            g_as[r] = sRed[0 * 128 + tid] + sRed[2 * 128 + tid];
            g_ad[r] = sRed[1 * 128 + tid] + sRed[3 * 128 + tid];
        }
    }
}

// -----------------------------------------------------------------------------
extern "C" void kernel_launch(void* const* d_in, const int* in_sizes, int n_in,
                              void* d_out, int out_size) {
    const float* x    = (const float*)d_in[0];
    const void*  ei   = d_in[1];
    const float* w1   = (const float*)d_in[2];
    const float* b1   = (const float*)d_in[3];
    const float* w2   = (const float*)d_in[4];
    const float* b2   = (const float*)d_in[5];
    const float* gatw = (const float*)d_in[6];
    const float* asrc = (const float*)d_in[7];
    const float* adst = (const float*)d_in[8];
    const float* gatb = (const float*)d_in[9];
    const float* fc1w = (const float*)d_in[10];
    const float* fc1b = (const float*)d_in[11];
    const float* fc2w = (const float*)d_in[12];
    const float* fc2b = (const float*)d_in[13];
    const float* fc3w = (const float*)d_in[14];
    const float* fc3b = (const float*)d_in[15];
    float* out = (float*)d_out;

    void *px3h, *pu1, *pu2, *pcc, *pw1t, *pw2t, *pw3t;
    cudaGetSymbolAddress(&px3h, g_x3h);
    cudaGetSymbolAddress(&pu1,  g_u1);
    cudaGetSymbolAddress(&pu2,  g_u2);
    cudaGetSymbolAddress(&pcc,  g_cc);
    cudaGetSymbolAddress(&pw1t, g_w1t);
    cudaGetSymbolAddress(&pw2t, g_w2t);
    cudaGetSymbolAddress(&pw3t, g_w3t);

    static cudaStream_t s2 = nullptr;
    static cudaEvent_t evFork = nullptr, evJoin = nullptr;
    if (!s2) {   // first call = correctness run (not captured): safe to create
        cudaStreamCreateWithFlags(&s2, cudaStreamNonBlocking);
        cudaEventCreateWithFlags(&evFork, cudaEventDisableTiming);
        cudaEventCreateWithFlags(&evJoin, cudaEventDisableTiming);
        cudaFuncSetAttribute(mlp_kernel, cudaFuncAttributeMaxDynamicSharedMemorySize, FM_SMEM);
        cudaFuncSetAttribute(h_gemm,     cudaFuncAttributeMaxDynamicSharedMemorySize, TS_SMEM);
    }

    const int GX = (NN + 127) / 128;   // 782

    // fused setup (stream 0): zero cnt + detect + prep + transposes
    setup_kernel<<<NZB + 3 + 192, 256>>>((const unsigned*)ei,
                                         w1, b1, w2, b2, gatb, fc1w, fc1b, fc2w, fc3w);

    // fork: CSR build on s2 concurrent with h GEMM on stream 0
    cudaEventRecord(evFork, 0);
    cudaStreamWaitEvent(s2, evFork, 0);
    hist_kernel<<<(EE + 255) / 256, 256, 0, s2>>>(ei);
    scan1_kernel<<<NSB, 256, 0, s2>>>();
    scan2_kernel<<<1, 256, 0, s2>>>();
    scan3_kernel<<<NSB, 512, 0, s2>>>();
    cudaEventRecord(evJoin, s2);

    // stream 0: h GEMM with fused alpha (smem reduce, no atomics)
    h_gemm<<<GX, 128, TS_SMEM>>>(x + 2, 130, gatw, 64, asrc, adst, NN);

    // join, then edge softmax + aggregation + fused MLP
    cudaStreamWaitEvent(0, evJoin, 0);
    scatter_kernel<<<(EE + 255) / 256, 256>>>(ei);
    agg_kernel<<<(NN * 32 + 255) / 256, 256>>>();
    mlp_kernel<<<GX, 256, FM_SMEM>>>((const __half*)px3h, x,
                                     (const __half*)pw1t, (const __half*)pw2t,
                                     (const __half*)pw3t,
                                     (const float*)pu1, (const float*)pu2,
                                     (const float*)pcc,
                                     fc2b, fc3b, out, NN);
}

// round 16
// speedup vs baseline: 1.1714x; 1.0735x over previous
#include <cuda_runtime.h>
#include <cuda_fp16.h>
#include <math.h>

#define NN 100000
#define EE 1600000
#define NSB ((NN + 511) / 512)   // 196 scan blocks
#define NZB ((NN + 255) / 256)   // 391 zero blocks

// ---------------- scratch (device globals; no allocation allowed) ------------
__device__ __half g_hh [(size_t)NN * 64];    // GAT h (fp16, for agg gather)
__device__ __half g_x3h[(size_t)NN * 64];    // aggregated GAT output (fp16)
__device__ float  g_as [NN];
__device__ float  g_ad [NN];
__device__ int    g_cnt[NN];                 // in-degree
__device__ int    g_off[NN];                 // CSR row offsets
__device__ int    g_rank[EE];                // per-edge rank within its dst bucket
__device__ float2 g_edge[EE];                // CSR (src bit-cast, exp) pairs
__device__ int    g_bsum[NSB], g_boff[NSB];
__device__ float  g_u1[384], g_u2[384], g_cc[384];
__device__ __half g_w1t[384 * 64];           // fc1_w[128:192,:]^T fp16 [n][k]
__device__ __half g_w2t[128 * 384];          // fc2_w^T fp16            [n][k]
__device__ __half g_w3t[64 * 128];           // fc3_w^T fp16            [n][k]
__device__ int    g_is64;

// ---------------- setup0: zero cnt + int64 detect (critical path) ------------
__global__ void setup0_kernel(const unsigned* __restrict__ p) {
    __shared__ unsigned sh[256];
    int b = blockIdx.x, t = threadIdx.x;
    if (b < NZB) {
        int i = b * 256 + t;
        if (i < NN) g_cnt[i] = 0;
        return;
    }
    // int64 detection: high words all zero => int64
    sh[t] = p[2 * t + 1];
    __syncthreads();
    if (t == 0) {
        unsigned o = 0;
        for (int i = 0; i < 256; i++) o |= sh[i];
        g_is64 = (o == 0) ? 1 : 0;
    }
}

// ---------------- setupW: prep rank-2 vectors + fp16 weight transposes -------
// Runs on its own stream; only needed before mlp_kernel.
__global__ void setupW_kernel(const float* __restrict__ w1, const float* __restrict__ b1,
                              const float* __restrict__ w2, const float* __restrict__ b2,
                              const float* __restrict__ gatb,
                              const float* __restrict__ fc1w, const float* __restrict__ fc1b,
                              const float* __restrict__ fc2w, const float* __restrict__ fc3w) {
    int b = blockIdx.x, t = threadIdx.x;
    if (b < 2) {   // prep: 192 cols per block
        if (t < 192) {
            int k = b * 192 + t;
            float s1 = 0.f, s2 = 0.f, c = fc1b[k];
            for (int j = 0; j < 64; j++) {
                float wa = fc1w[(size_t)j * 384 + k];
                float wb = fc1w[(size_t)(64 + j) * 384 + k];
                float wc = fc1w[(size_t)(128 + j) * 384 + k];
                s1 += w1[j] * wa;
                s2 += w2[j] * wb;
                c  += b1[j] * wa + b2[j] * wb + gatb[j] * wc;
            }
            g_u1[k] = s1; g_u2[k] = s2; g_cc[k] = c;
        }
        return;
    }
    int i = (b - 2) * 256 + t;
    if (i < 384 * 64) {                       // g_w1t[c][k] = fc1w[128+k][c]
        int c = i >> 6, k = i & 63;
        g_w1t[i] = __float2half_rn(fc1w[(size_t)(128 + k) * 384 + c]);
    }
    if (i < 128 * 384) {                      // g_w2t[c][k] = fc2w[k][c]
        int c = i / 384, k = i % 384;
        g_w2t[i] = __float2half_rn(fc2w[(size_t)k * 128 + c]);
    }
    if (i < 64 * 128) {                       // g_w3t[c][k] = fc3w[k][c]
        int c = i >> 7, k = i & 127;
        g_w3t[i] = __float2half_rn(fc3w[(size_t)k * 64 + c]);
    }
}

// ---------------- degree histogram + rank assignment --------------------------
__global__ void hist_kernel(const void* __restrict__ idx) {
    int e = blockIdx.x * blockDim.x + threadIdx.x;
    if (e >= EE) return;
    int d = g_is64 ? (int)((const long long*)idx)[EE + e]
                   : ((const int*)idx)[EE + e];
    g_rank[e] = atomicAdd(&g_cnt[d], 1);
}

// ---------------- 3-kernel exclusive scan over g_cnt -------------------------
__global__ void scan1_kernel() {
    __shared__ int sh[256];
    int b = blockIdx.x, t = threadIdx.x;
    int i0 = b * 512 + t;
    int v = 0;
    if (i0 < NN) v += g_cnt[i0];
    if (i0 + 256 < NN) v += g_cnt[i0 + 256];
    sh[t] = v; __syncthreads();
    for (int o = 128; o; o >>= 1) { if (t < o) sh[t] += sh[t + o]; __syncthreads(); }
    if (t == 0) g_bsum[b] = sh[0];
}

__global__ void scan2_kernel() {
    __shared__ int sh[256];
    int t = threadIdx.x;
    int v = (t < NSB) ? g_bsum[t] : 0;
    sh[t] = v;
    for (int o = 1; o < 256; o <<= 1) {
        __syncthreads();
        int u = (t >= o) ? sh[t - o] : 0;
        __syncthreads();
        sh[t] += u;
    }
    __syncthreads();
    if (t < NSB) g_boff[t] = sh[t] - v;
}

__global__ void scan3_kernel() {
    __shared__ int sh[512];
    int b = blockIdx.x, t = threadIdx.x;
    int i = b * 512 + t;
    int c = (i < NN) ? g_cnt[i] : 0;
    sh[t] = c;
    for (int o = 1; o < 512; o <<= 1) {
        __syncthreads();
        int u = (t >= o) ? sh[t - o] : 0;
        __syncthreads();
        sh[t] += u;
    }
    __syncthreads();
    if (i < NN) g_off[i] = sh[t] - c + g_boff[b];
}

// ---------------- scatter into CSR: atomic-free via precomputed rank ---------
__global__ void scatter_kernel(const void* __restrict__ idx) {
    int e = blockIdx.x * blockDim.x + threadIdx.x;
    if (e >= EE) return;
    int s, d;
    if (g_is64) {
        const long long* q = (const long long*)idx;
        s = (int)q[e]; d = (int)q[EE + e];
    } else {
        const int* q = (const int*)idx;
        s = q[e]; d = q[EE + e];
    }
    float v = g_as[s] + g_ad[d];
    v = (v > 0.f) ? v : 0.2f * v;
    float ex = expf(v);
    int p = g_off[d] + g_rank[e];
    g_edge[p] = make_float2(__int_as_float(s), ex);
}

// ---------------- CSR aggregation: warp per node, fp16 gather ----------------
__global__ void agg_kernel() {
    int node = (int)((blockIdx.x * (size_t)blockDim.x + threadIdx.x) >> 5);
    int lane = threadIdx.x & 31;
    if (node >= NN) return;
    int beg = g_off[node];
    int cnt = g_cnt[node];
    float v = g_as[node] + g_ad[node];
    v = (v > 0.f) ? v : 0.2f * v;
    float ex_self = expf(v);
    // denominator from precomputed contiguous ex stream
    float dsum = 0.f;
    for (int i = lane; i < cnt; i += 32) dsum += g_edge[beg + i].y;
#pragma unroll
    for (int o = 16; o; o >>= 1) dsum += __shfl_xor_sync(0xffffffffu, dsum, o);
    float invd = 1.f / (dsum + ex_self + 1e-16f);
    float2 acc;
    {
        half2 hv = *(const half2*)(g_hh + (size_t)node * 64 + lane * 2);
        float2 f = __half22float2(hv);
        float c = ex_self * invd;
        acc.x = c * f.x; acc.y = c * f.y;
    }
#pragma unroll 4
    for (int e = 0; e < cnt; e++) {
        float2 ev = g_edge[beg + e];
        int s = __float_as_int(ev.x);
        float c = ev.y * invd;
        half2 hv = *(const half2*)(g_hh + (size_t)s * 64 + lane * 2);
        float2 f = __half22float2(hv);
        acc.x += c * f.x; acc.y += c * f.y;
    }
    *(half2*)(g_x3h + (size_t)node * 64 + lane * 2) = __floats2half2_rn(acc.x, acc.y);
}

// ---------------- TF32 / fp16 / cp.async helpers -------------------------------
__device__ __forceinline__ unsigned f2tf(float x) {
    unsigned r; asm("cvt.rna.tf32.f32 %0, %1;" : "=r"(r) : "f"(x)); return r;
}
__device__ __forceinline__ void mma_tf32(float* d, const unsigned* a, const unsigned* b) {
    asm volatile(
        "mma.sync.aligned.m16n8k8.row.col.f32.tf32.tf32.f32 "
        "{%0,%1,%2,%3}, {%4,%5,%6,%7}, {%8,%9}, {%0,%1,%2,%3};\n"
        : "+f"(d[0]), "+f"(d[1]), "+f"(d[2]), "+f"(d[3])
        : "r"(a[0]), "r"(a[1]), "r"(a[2]), "r"(a[3]), "r"(b[0]), "r"(b[1]));
}
__device__ __forceinline__ void mma_f16(float* d, const unsigned* a, const unsigned* b) {
    asm volatile(
        "mma.sync.aligned.m16n8k16.row.col.f32.f16.f16.f32 "
        "{%0,%1,%2,%3}, {%4,%5,%6,%7}, {%8,%9}, {%0,%1,%2,%3};\n"
        : "+f"(d[0]), "+f"(d[1]), "+f"(d[2]), "+f"(d[3])
        : "r"(a[0]), "r"(a[1]), "r"(a[2]), "r"(a[3]), "r"(b[0]), "r"(b[1]));
}
__device__ __forceinline__ void cp16(void* smem, const void* g, bool valid) {
    unsigned sa = (unsigned)__cvta_generic_to_shared(smem);
    int sz = valid ? 16 : 0;
    asm volatile("cp.async.cg.shared.global [%0], [%1], 16, %2;" :: "r"(sa), "l"(g), "r"(sz));
}
__device__ __forceinline__ void cp8(void* smem, const void* g, bool valid) {
    unsigned sa = (unsigned)__cvta_generic_to_shared(smem);
    int sz = valid ? 8 : 0;
    asm volatile("cp.async.ca.shared.global [%0], [%1], 8, %2;" :: "r"(sa), "l"(g), "r"(sz));
}
#define CP_COMMIT() asm volatile("cp.async.commit_group;")
#define CP_WAIT1()  asm volatile("cp.async.wait_group 1;")
#define CP_WAIT0()  asm volatile("cp.async.wait_group 0;")

// ---------------- fused MLP: fc1 -> fc2 -> fc3, 256 threads -------------------
#define FM_WSZ   (128 * 72)
#define FM_SMEM  ((68608 + 9216) * 2 + 1024)   // 156672 bytes
__global__ void __launch_bounds__(256)
mlp_kernel(const __half* __restrict__ x3h, const float* __restrict__ x,
           const __half* __restrict__ w1t, const __half* __restrict__ w2t,
           const __half* __restrict__ w3t,
           const float* __restrict__ u1, const float* __restrict__ u2,
           const float* __restrict__ cc,
           const float* __restrict__ fc2b, const float* __restrict__ fc3b,
           float* __restrict__ out, int n) {
    extern __shared__ __half sm[];
    __half* sH1 = sm;                       // [128][392]
    __half* sW  = sm + 50176;               // 2 x [128][72]
    __half* sA  = sm + 68608;               // [128][72]
    float*  sXR = (float*)(sm + 77824);     // [128][2]

    const int tid = threadIdx.x;
    const int warp = tid >> 5, lane = tid & 31;
    const int wm = warp >> 2, wn = warp & 3;
    const int grp = lane >> 2, qid = lane & 3;
    const int row0 = blockIdx.x * 128;

    auto load_w = [&](int t, int b) {
        __half* dst = sW + b * FM_WSZ;
        if (t < 3) {
            const __half* src = w1t + (size_t)t * 128 * 64;
#pragma unroll
            for (int l = 0; l < 4; l++) {
                int i = tid + l * 256; int r = i >> 3, c8 = (i & 7) * 8;
                cp16(&dst[r * 72 + c8], src + r * 64 + c8, true);
            }
        } else if (t < 9) {
            int kk = (t - 3) * 64;
#pragma unroll
            for (int l = 0; l < 4; l++) {
                int i = tid + l * 256; int r = i >> 3, c8 = (i & 7) * 8;
                cp16(&dst[r * 72 + c8], w2t + (size_t)r * 384 + kk + c8, true);
            }
        } else {
#pragma unroll
            for (int l = 0; l < 4; l++) {
                int i = tid + l * 256; int r = i >> 4, c8 = (i & 15) * 8;
                cp16(&dst[r * 136 + c8], w3t + (size_t)r * 128 + c8, true);
            }
        }
    };

#pragma unroll
    for (int l = 0; l < 4; l++) {
        int i = tid + l * 256; int r = i >> 3, c8 = (i & 7) * 8;
        bool v = row0 + r < n;
        cp16(&sA[r * 72 + c8], x3h + (size_t)(v ? row0 + r : 0) * 64 + c8, v);
    }
    if (tid < 128) {
        bool v = row0 + tid < n;
        cp8(&sXR[tid * 2], x + (size_t)(v ? row0 + tid : 0) * 130, v);
    }
    load_w(0, 0); CP_COMMIT();
    load_w(1, 1); CP_COMMIT();

    // ---- stage 1: fc1 (K=64), 3 output chunks of 128 cols -> sH1 fp16 ----
    for (int j = 0; j < 3; j++) {
        CP_WAIT1(); __syncthreads();
        const __half* Bt = sW + (j & 1) * FM_WSZ;
        float acc[4][4][4] = {};
#pragma unroll
        for (int ks = 0; ks < 4; ks++) {
            const int k0 = ks * 16;
            unsigned a[4][4], b[4][2];
#pragma unroll
            for (int mf = 0; mf < 4; mf++) {
                int r = wm * 64 + mf * 16 + grp;
                a[mf][0] = *(const unsigned*)&sA[r * 72 + k0 + 2 * qid];
                a[mf][1] = *(const unsigned*)&sA[(r + 8) * 72 + k0 + 2 * qid];
                a[mf][2] = *(const unsigned*)&sA[r * 72 + k0 + 2 * qid + 8];
                a[mf][3] = *(const unsigned*)&sA[(r + 8) * 72 + k0 + 2 * qid + 8];
            }
#pragma unroll
            for (int nf = 0; nf < 4; nf++) {
                int c = wn * 32 + nf * 8 + grp;
                b[nf][0] = *(const unsigned*)&Bt[c * 72 + k0 + 2 * qid];
                b[nf][1] = *(const unsigned*)&Bt[c * 72 + k0 + 2 * qid + 8];
            }
#pragma unroll
            for (int mf = 0; mf < 4; mf++)
#pragma unroll
                for (int nf = 0; nf < 4; nf++)
                    mma_f16(acc[mf][nf], a[mf], b[nf]);
        }
#pragma unroll
        for (int mf = 0; mf < 4; mf++)
#pragma unroll
            for (int hi = 0; hi < 2; hi++) {
                int rl = wm * 64 + mf * 16 + grp + hi * 8;
                float xa = sXR[rl * 2], xb = sXR[rl * 2 + 1];
#pragma unroll
                for (int nf = 0; nf < 4; nf++) {
                    int c = wn * 32 + nf * 8 + qid * 2;
                    int gc = j * 128 + c;
                    float v0 = acc[mf][nf][hi * 2 + 0] + xa * u1[gc] + xb * u2[gc] + cc[gc];
                    float v1 = acc[mf][nf][hi * 2 + 1] + xa * u1[gc + 1] + xb * u2[gc + 1] + cc[gc + 1];
                    v0 = fmaxf(v0, 0.f); v1 = fmaxf(v1, 0.f);
                    *(half2*)&sH1[rl * 392 + gc] = __floats2half2_rn(v0, v1);
                }
            }
        __syncthreads();
        load_w(j + 2, j & 1); CP_COMMIT();
    }

    // ---- stage 2: fc2 (K=384 from sH1) ----
    float acc2[4][4][4] = {};
    for (int kc = 0; kc < 6; kc++) {
        CP_WAIT1(); __syncthreads();
        const __half* Bt = sW + ((kc + 3) & 1) * FM_WSZ;
#pragma unroll
        for (int ks = 0; ks < 4; ks++) {
            const int k0 = kc * 64 + ks * 16;
            const int kb = ks * 16;
            unsigned a[4][4], b[4][2];
#pragma unroll
            for (int mf = 0; mf < 4; mf++) {
                int r = wm * 64 + mf * 16 + grp;
                a[mf][0] = *(const unsigned*)&sH1[r * 392 + k0 + 2 * qid];
                a[mf][1] = *(const unsigned*)&sH1[(r + 8) * 392 + k0 + 2 * qid];
                a[mf][2] = *(const unsigned*)&sH1[r * 392 + k0 + 2 * qid + 8];
                a[mf][3] = *(const unsigned*)&sH1[(r + 8) * 392 + k0 + 2 * qid + 8];
            }
#pragma unroll
            for (int nf = 0; nf < 4; nf++) {
                int c = wn * 32 + nf * 8 + grp;
                b[nf][0] = *(const unsigned*)&Bt[c * 72 + kb + 2 * qid];
                b[nf][1] = *(const unsigned*)&Bt[c * 72 + kb + 2 * qid + 8];
            }
#pragma unroll
            for (int mf = 0; mf < 4; mf++)
#pragma unroll
                for (int nf = 0; nf < 4; nf++)
                    mma_f16(acc2[mf][nf], a[mf], b[nf]);
        }
        __syncthreads();
        int t = kc + 5;
        if (t <= 9) { load_w(t, (kc + 3) & 1); CP_COMMIT(); }
    }

    // ---- stage 2 epilogue -> sH2 fp16 (reuses sH1) ----
    __half* sH2 = sH1;
#pragma unroll
    for (int mf = 0; mf < 4; mf++)
#pragma unroll
        for (int hi = 0; hi < 2; hi++) {
            int rl = wm * 64 + mf * 16 + grp + hi * 8;
#pragma unroll
            for (int nf = 0; nf < 4; nf++) {
                int c = wn * 32 + nf * 8 + qid * 2;
                float v0 = fmaxf(acc2[mf][nf][hi * 2 + 0] + fc2b[c], 0.f);
                float v1 = fmaxf(acc2[mf][nf][hi * 2 + 1] + fc2b[c + 1], 0.f);
                *(half2*)&sH2[rl * 136 + c] = __floats2half2_rn(v0, v1);
            }
        }
    CP_WAIT0(); __syncthreads();

    // ---- stage 3: fc3 (K=128 from sH2) -> out fp32 ----
    {
        const __half* Bt = sW + 1 * FM_WSZ;
        float acc3[4][2][4] = {};
#pragma unroll
        for (int ks = 0; ks < 8; ks++) {
            const int k0 = ks * 16;
            unsigned a[4][4], b[2][2];
#pragma unroll
            for (int mf = 0; mf < 4; mf++) {
                int r = wm * 64 + mf * 16 + grp;
                a[mf][0] = *(const unsigned*)&sH2[r * 136 + k0 + 2 * qid];
                a[mf][1] = *(const unsigned*)&sH2[(r + 8) * 136 + k0 + 2 * qid];
                a[mf][2] = *(const unsigned*)&sH2[r * 136 + k0 + 2 * qid + 8];
                a[mf][3] = *(const unsigned*)&sH2[(r + 8) * 136 + k0 + 2 * qid + 8];
            }
#pragma unroll
            for (int nf = 0; nf < 2; nf++) {
                int c = wn * 16 + nf * 8 + grp;
                b[nf][0] = *(const unsigned*)&Bt[c * 136 + k0 + 2 * qid];
                b[nf][1] = *(const unsigned*)&Bt[c * 136 + k0 + 2 * qid + 8];
            }
#pragma unroll
            for (int mf = 0; mf < 4; mf++)
#pragma unroll
                for (int nf = 0; nf < 2; nf++)
                    mma_f16(acc3[mf][nf], a[mf], b[nf]);
        }
#pragma unroll
        for (int mf = 0; mf < 4; mf++)
#pragma unroll
            for (int hi = 0; hi < 2; hi++) {
                int r = row0 + wm * 64 + mf * 16 + grp + hi * 8;
                if (r >= n) continue;
#pragma unroll
                for (int nf = 0; nf < 2; nf++) {
                    int c = wn * 16 + nf * 8 + qid * 2;
                    float v0 = acc3[mf][nf][hi * 2 + 0] + fc3b[c];
                    float v1 = acc3[mf][nf][hi * 2 + 1] + fc3b[c + 1];
                    *(float2*)&out[(size_t)r * 64 + c] = make_float2(v0, v1);
                }
            }
    }
}

// ---------------- h GEMM: split 3xTF32, fused alpha (smem reduce) -------------
#define TS_ASZ (128 * 36)
#define TS_BSZ (32 * 72)
#define TS_RED (2 * 2 * 128)
#define TS_SMEM (((2 * (TS_ASZ + TS_BSZ)) + TS_RED) * 4)
__global__ void __launch_bounds__(128)
h_gemm(const float* __restrict__ A, int lda,
       const float* __restrict__ W, int ldw,
       const float* __restrict__ asrc, const float* __restrict__ adst,
       int n) {
    constexpr int BM = 128, BK = 32;
    extern __shared__ float smem[];
    float* Asf = smem;
    float* Bsf = smem + 2 * TS_ASZ;
    float* sRed = smem + 2 * (TS_ASZ + TS_BSZ);   // [2][2][128]

    const int tid = threadIdx.x;
    const int warp = tid >> 5, lane = tid & 31;
    const int wm = warp >> 1;
    const int wn = warp & 1;
    const int grp = lane >> 2, qid = lane & 3;
    const int row0 = blockIdx.x * BM;
    const int nk = 128 / BK;

    float acc[4][4][4] = {};

    auto load_tile = [&](int s, int kk) {
        float* At = Asf + s * TS_ASZ;
        float* Bt = Bsf + s * TS_BSZ;
#pragma unroll
        for (int l = 0; l < 16; l++) {
            int i = tid + l * 128;
            int r = i >> 4, c2 = (i & 15) * 2;
            int gr = row0 + r;
            bool v = gr < n;
            cp8(&At[r * 36 + c2], A + (size_t)(v ? gr : n - 1) * lda + kk + c2, v);
        }
#pragma unroll
        for (int l = 0; l < 4; l++) {
            int i = tid + l * 128;
            int r = i >> 4, c4 = (i & 15) * 4;
            cp16(&Bt[r * 72 + c4], &W[(size_t)(kk + r) * ldw + c4], true);
        }
        CP_COMMIT();
    };

    load_tile(0, 0);
    for (int t = 0; t < nk; t++) {
        if (t + 1 < nk) load_tile((t + 1) & 1, (t + 1) * BK);
        if (t + 1 < nk) CP_WAIT1(); else CP_WAIT0();
        __syncthreads();
        const float* At = Asf + (t & 1) * TS_ASZ;
        const float* Bt = Bsf + (t & 1) * TS_BSZ;
#pragma unroll
        for (int ks = 0; ks < BK / 8; ks++) {
            const int k0 = ks * 8;
            unsigned ah[4][4], al[4][4], bh[4][2], bl[4][2];
#pragma unroll
            for (int mf = 0; mf < 4; mf++) {
                int r = wm * 64 + mf * 16 + grp;
                float x0 = At[r * 36 + k0 + qid];
                float x1 = At[(r + 8) * 36 + k0 + qid];
                float x2 = At[r * 36 + k0 + qid + 4];
                float x3 = At[(r + 8) * 36 + k0 + qid + 4];
                ah[mf][0] = f2tf(x0); al[mf][0] = f2tf(x0 - __uint_as_float(ah[mf][0]));
                ah[mf][1] = f2tf(x1); al[mf][1] = f2tf(x1 - __uint_as_float(ah[mf][1]));
                ah[mf][2] = f2tf(x2); al[mf][2] = f2tf(x2 - __uint_as_float(ah[mf][2]));
                ah[mf][3] = f2tf(x3); al[mf][3] = f2tf(x3 - __uint_as_float(ah[mf][3]));
            }
#pragma unroll
            for (int nf = 0; nf < 4; nf++) {
                int c = wn * 32 + nf * 8 + grp;
                float y0 = Bt[(k0 + qid) * 72 + c];
                float y1 = Bt[(k0 + qid + 4) * 72 + c];
                bh[nf][0] = f2tf(y0); bl[nf][0] = f2tf(y0 - __uint_as_float(bh[nf][0]));
                bh[nf][1] = f2tf(y1); bl[nf][1] = f2tf(y1 - __uint_as_float(bh[nf][1]));
            }
#pragma unroll
            for (int mf = 0; mf < 4; mf++)
#pragma unroll
                for (int nf = 0; nf < 4; nf++) {
                    mma_tf32(acc[mf][nf], al[mf], bh[nf]);
                    mma_tf32(acc[mf][nf], ah[mf], bl[nf]);
                    mma_tf32(acc[mf][nf], ah[mf], bh[nf]);
                }
        }
        __syncthreads();
    }

    // epilogue: fp16 h write + alpha partial dots -> smem reduce -> stores
#pragma unroll
    for (int mf = 0; mf < 4; mf++) {
#pragma unroll
        for (int hi = 0; hi < 2; hi++) {
            int rl = wm * 64 + mf * 16 + grp + hi * 8;
            int r = row0 + rl;
            bool valid = r < n;
            float sp = 0.f, dp = 0.f;
#pragma unroll
            for (int nf = 0; nf < 4; nf++) {
                int c = wn * 32 + nf * 8 + qid * 2;
                float v0 = acc[mf][nf][hi * 2 + 0];
                float v1 = acc[mf][nf][hi * 2 + 1];
                if (valid)
                    *(half2*)&g_hh[(size_t)r * 64 + c] = __floats2half2_rn(v0, v1);
                sp += v0 * asrc[c] + v1 * asrc[c + 1];
                dp += v0 * adst[c] + v1 * adst[c + 1];
            }
            sp += __shfl_xor_sync(0xffffffffu, sp, 1);
            sp += __shfl_xor_sync(0xffffffffu, sp, 2);
            dp += __shfl_xor_sync(0xffffffffu, dp, 1);
            dp += __shfl_xor_sync(0xffffffffu, dp, 2);
            if (qid == 0) {
                sRed[(wn * 2 + 0) * 128 + rl] = sp;
                sRed[(wn * 2 + 1) * 128 + rl] = dp;
            }
        }
    }
    __syncthreads();
    if (tid < 128) {
        int r = row0 + tid;
        if (r < n) {
            g_as[r] = sRed[0 * 128 + tid] + sRed[2 * 128 + tid];
            g_ad[r] = sRed[1 * 128 + tid] + sRed[3 * 128 + tid];
        }
    }
}

// -----------------------------------------------------------------------------
extern "C" void kernel_launch(void* const* d_in, const int* in_sizes, int n_in,
                              void* d_out, int out_size) {
    const float* x    = (const float*)d_in[0];
    const void*  ei   = d_in[1];
    const float* w1   = (const float*)d_in[2];
    const float* b1   = (const float*)d_in[3];
    const float* w2   = (const float*)d_in[4];
    const float* b2   = (const float*)d_in[5];
    const float* gatw = (const float*)d_in[6];
    const float* asrc = (const float*)d_in[7];
    const float* adst = (const float*)d_in[8];
    const float* gatb = (const float*)d_in[9];
    const float* fc1w = (const float*)d_in[10];
    const float* fc1b = (const float*)d_in[11];
    const float* fc2w = (const float*)d_in[12];
    const float* fc2b = (const float*)d_in[13];
    const float* fc3w = (const float*)d_in[14];
    const float* fc3b = (const float*)d_in[15];
    float* out = (float*)d_out;

    void *px3h, *pu1, *pu2, *pcc, *pw1t, *pw2t, *pw3t;
    cudaGetSymbolAddress(&px3h, g_x3h);
    cudaGetSymbolAddress(&pu1,  g_u1);
    cudaGetSymbolAddress(&pu2,  g_u2);
    cudaGetSymbolAddress(&pcc,  g_cc);
    cudaGetSymbolAddress(&pw1t, g_w1t);
    cudaGetSymbolAddress(&pw2t, g_w2t);
    cudaGetSymbolAddress(&pw3t, g_w3t);

    static cudaStream_t s2 = nullptr, s3 = nullptr;
    static cudaEvent_t evFork0 = nullptr, evFork = nullptr, evJoin = nullptr, evW = nullptr;
    if (!s2) {   // first call = correctness run (not captured): safe to create
        cudaStreamCreateWithFlags(&s2, cudaStreamNonBlocking);
        cudaStreamCreateWithFlags(&s3, cudaStreamNonBlocking);
        cudaEventCreateWithFlags(&evFork0, cudaEventDisableTiming);
        cudaEventCreateWithFlags(&evFork,  cudaEventDisableTiming);
        cudaEventCreateWithFlags(&evJoin,  cudaEventDisableTiming);
        cudaEventCreateWithFlags(&evW,     cudaEventDisableTiming);
        cudaFuncSetAttribute(mlp_kernel, cudaFuncAttributeMaxDynamicSharedMemorySize, FM_SMEM);
        cudaFuncSetAttribute(h_gemm,     cudaFuncAttributeMaxDynamicSharedMemorySize, TS_SMEM);
    }

    const int GX = (NN + 127) / 128;   // 782

    // fork s3 immediately: weight prep depends only on inputs
    cudaEventRecord(evFork0, 0);
    cudaStreamWaitEvent(s3, evFork0, 0);
    setupW_kernel<<<2 + 192, 256, 0, s3>>>(w1, b1, w2, b2, gatb, fc1w, fc1b, fc2w, fc3w);
    cudaEventRecord(evW, s3);

    // critical setup: zero cnt + int64 detect
    setup0_kernel<<<NZB + 1, 256>>>((const unsigned*)ei);

    // fork s2: CSR build (hist assigns ranks) concurrent with h GEMM
    cudaEventRecord(evFork, 0);
    cudaStreamWaitEvent(s2, evFork, 0);
    hist_kernel<<<(EE + 255) / 256, 256, 0, s2>>>(ei);
    scan1_kernel<<<NSB, 256, 0, s2>>>();
    scan2_kernel<<<1, 256, 0, s2>>>();
    scan3_kernel<<<NSB, 512, 0, s2>>>();
    cudaEventRecord(evJoin, s2);

    // stream 0: h GEMM with fused alpha
    h_gemm<<<GX, 128, TS_SMEM>>>(x + 2, 130, gatw, 64, asrc, adst, NN);

    // join CSR, then atomic-free scatter + aggregation
    cudaStreamWaitEvent(0, evJoin, 0);
    scatter_kernel<<<(EE + 255) / 256, 256>>>(ei);
    agg_kernel<<<(NN * 32 + 255) / 256, 256>>>();

    // join weight prep, then fused MLP
    cudaStreamWaitEvent(0, evW, 0);
    mlp_kernel<<<GX, 256, FM_SMEM>>>((const __half*)px3h, x,
                                     (const __half*)pw1t, (const __half*)pw2t,
                                     (const __half*)pw3t,
                                     (const float*)pu1, (const float*)pu2,
                                     (const float*)pcc,
                                     fc2b, fc3b, out, NN);
}